// round 3
// baseline (speedup 1.0000x reference)
#include <cuda_runtime.h>

#define NF      26
#define EMB     128
#define ROW_IN  (NF * EMB)            // 3328
#define NPAIR   325                   // 26*25/2
#define DENSE   128
#define ROW_OUT (ROW_IN + NPAIR + DENSE) // 3781
#define NTILE   7                     // ceil(26/4)
#define NTP     28                    // tile pairs (ti<=tj)

// tile-pair table (ti<=tj over 7 feature tiles of 4), statically initialized
__constant__ unsigned char c_tp[NTP][2] = {
    {0,0},{0,1},{0,2},{0,3},{0,4},{0,5},{0,6},
    {1,1},{1,2},{1,3},{1,4},{1,5},{1,6},
    {2,2},{2,3},{2,4},{2,5},{2,6},
    {3,3},{3,4},{3,5},{3,6},
    {4,4},{4,5},{4,6},
    {5,5},{5,6},
    {6,6}
};

__device__ __forceinline__ int pair_index(int f, int g) {
    // index into upper triangle (k=1), row-major over (f<g)
    return f * 25 - (f * (f - 1)) / 2 + (g - f - 1);
}

__global__ __launch_bounds__(256, 8)
void fi_kernel(const float* __restrict__ sparse,
               const float* __restrict__ dense,
               float* __restrict__ out)
{
    __shared__ float s_emb[ROW_IN];      // 26 x 128, rows 512B-aligned
    __shared__ float s_int[NPAIR + 3];   // staged interactions

    const int r   = blockIdx.x;
    const int tid = threadIdx.x;

    const float4* __restrict__ in4 = (const float4*)(sparse + (size_t)r * ROW_IN);
    float* __restrict__ orow = out + (size_t)r * ROW_OUT;

    // ---- Phase 1: load sparse row into smem, fused passthrough copy ----
    #pragma unroll 2
    for (int i = tid; i < ROW_IN / 4; i += 256) {
        float4 v = in4[i];
        ((float4*)s_emb)[i] = v;
        // out row base alignment varies with r (3781 % 4 == 1) -> scalar stores
        int o = 4 * i;
        orow[o + 0] = v.x;
        orow[o + 1] = v.y;
        orow[o + 2] = v.z;
        orow[o + 3] = v.w;
    }

    // dense passthrough
    if (tid < DENSE) {
        orow[ROW_IN + NPAIR + tid] = dense[(size_t)r * DENSE + tid];
    }

    __syncthreads();

    // ---- Phase 2: gram upper triangle, warp per 4x4 feature tile ----
    const int warp = tid >> 5;
    const int lane = tid & 31;

    for (int tp = warp; tp < NTP; tp += 8) {
        const int ti = c_tp[tp][0];
        const int tj = c_tp[tp][1];
        const int f0 = ti * 4;
        const int g0 = tj * 4;

        float4 A[4], B[4];
        #pragma unroll
        for (int a = 0; a < 4; a++) {
            int f = f0 + a;
            A[a] = (f < NF) ? ((const float4*)(s_emb + f * EMB))[lane]
                            : make_float4(0.f, 0.f, 0.f, 0.f);
        }
        if (ti == tj) {
            #pragma unroll
            for (int b = 0; b < 4; b++) B[b] = A[b];
        } else {
            #pragma unroll
            for (int b = 0; b < 4; b++) {
                int g = g0 + b;
                B[b] = (g < NF) ? ((const float4*)(s_emb + g * EMB))[lane]
                                : make_float4(0.f, 0.f, 0.f, 0.f);
            }
        }

        #pragma unroll
        for (int a = 0; a < 4; a++) {
            #pragma unroll
            for (int b = 0; b < 4; b++) {
                const int f = f0 + a;
                const int g = g0 + b;
                if (f < g && g < NF) {           // warp-uniform predicate
                    float4 x = A[a], y = B[b];
                    float p = x.x * y.x + x.y * y.y + x.z * y.z + x.w * y.w;
                    p += __shfl_xor_sync(0xFFFFFFFFu, p, 16);
                    p += __shfl_xor_sync(0xFFFFFFFFu, p, 8);
                    p += __shfl_xor_sync(0xFFFFFFFFu, p, 4);
                    p += __shfl_xor_sync(0xFFFFFFFFu, p, 2);
                    p += __shfl_xor_sync(0xFFFFFFFFu, p, 1);
                    if (lane == 0) s_int[pair_index(f, g)] = p;
                }
            }
        }
    }

    __syncthreads();

    // ---- Phase 3: coalesced flush of interactions ----
    #pragma unroll 2
    for (int i = tid; i < NPAIR; i += 256) {
        orow[ROW_IN + i] = s_int[i];
    }
}

extern "C" void kernel_launch(void* const* d_in, const int* in_sizes, int n_in,
                              void* d_out, int out_size)
{
    const float* sparse = (const float*)d_in[0];
    const float* dense  = (const float*)d_in[1];
    float* out = (float*)d_out;

    const int batch = in_sizes[0] / ROW_IN;   // 16384
    fi_kernel<<<batch, 256>>>(sparse, dense, out);
}

// round 8
// speedup vs baseline: 1.0032x; 1.0032x over previous
#include <cuda_runtime.h>

#define NF      26
#define EMB     128
#define ROW_IN  (NF * EMB)               // 3328
#define NPAIR   325                      // 26*25/2
#define DENSE   128
#define ROW_OUT (ROW_IN + NPAIR + DENSE) // 3781
#define WPB     8                        // warps (rows) per block

// Multi-value butterfly reduction: vals[0..31] are per-lane partials of 32
// distinct outputs. After 31 shuffles, lane j holds the full sum of output j
// in vals[0]. Store directly (coalesced).
__device__ __forceinline__ void flush32(float vals[32], float* __restrict__ dst,
                                        int lane, int count)
{
    #pragma unroll
    for (int m = 16; m >= 1; m >>= 1) {
        #pragma unroll
        for (int i = 0; i < m; i++) {
            const bool hi  = (lane & m) != 0;
            float send = hi ? vals[i]     : vals[i + m];
            float keep = hi ? vals[i + m] : vals[i];
            float recv = __shfl_xor_sync(0xFFFFFFFFu, send, m);
            vals[i] = keep + recv;
        }
    }
    if (lane < count) dst[lane] = vals[0];
}

__global__ __launch_bounds__(256, 5)
void fi_kernel(const float* __restrict__ sparse,
               const float* __restrict__ dense,
               float* __restrict__ out,
               int batch)
{
    const int warp = threadIdx.x >> 5;
    const int lane = threadIdx.x & 31;
    const int r = blockIdx.x * WPB + warp;
    if (r >= batch) return;

    const float4* __restrict__ in4 = (const float4*)(sparse + (size_t)r * ROW_IN);
    float* __restrict__ orow = out + (size_t)r * ROW_OUT;

    // ---- Load entire row into registers: lane l holds elems [4l,4l+4) of every feature ----
    float4 A[NF];
    #pragma unroll
    for (int f = 0; f < NF; f++) {
        A[f] = in4[f * (EMB / 4) + lane];
    }

    // ---- Sparse passthrough straight from registers (scalar: out row base is r mod 4 aligned) ----
    #pragma unroll
    for (int f = 0; f < NF; f++) {
        const int o = f * EMB + lane * 4;
        orow[o + 0] = A[f].x;
        orow[o + 1] = A[f].y;
        orow[o + 2] = A[f].z;
        orow[o + 3] = A[f].w;
    }

    // ---- Dense passthrough ----
    {
        float4 dv = ((const float4*)(dense + (size_t)r * DENSE))[lane];
        const int o = ROW_IN + NPAIR + lane * 4;
        orow[o + 0] = dv.x;
        orow[o + 1] = dv.y;
        orow[o + 2] = dv.z;
        orow[o + 3] = dv.w;
    }

    // ---- Gram upper triangle: 325 per-lane partial dots, flushed in batches of 32 ----
    float vals[32];
    int cnt = 0;       // constant-folded under full unroll
    int base = 0;
    float* __restrict__ ip = orow + ROW_IN;

    #pragma unroll
    for (int f = 0; f < NF - 1; f++) {
        #pragma unroll
        for (int g = f + 1; g < NF; g++) {
            const float4 x = A[f];
            const float4 y = A[g];
            vals[cnt] = x.x * y.x + x.y * y.y + x.z * y.z + x.w * y.w;
            cnt++;
            if (cnt == 32) {
                flush32(vals, ip + base, lane, 32);
                base += 32;
                cnt = 0;
            }
        }
    }
    if (cnt > 0) {
        flush32(vals, ip + base, lane, cnt);   // tail: 325 % 32 = 5
    }
}

extern "C" void kernel_launch(void* const* d_in, const int* in_sizes, int n_in,
                              void* d_out, int out_size)
{
    const float* sparse = (const float*)d_in[0];
    const float* dense  = (const float*)d_in[1];
    float* out = (float*)d_out;

    const int batch = in_sizes[0] / ROW_IN;          // 16384
    const int grid  = (batch + WPB - 1) / WPB;       // 2048
    fi_kernel<<<grid, WPB * 32>>>(sparse, dense, out, batch);
}